// round 4
// baseline (speedup 1.0000x reference)
#include <cuda_runtime.h>
#include <math.h>

#define BB 8192
#define VV 100000
#define DD 64
#define ND 15
#define SL 50
#define FF 16
#define HID 30
#define PAIRS 120
#define IN_DIM (FF*DD + PAIRS)   /* 1144 */
#define W1T_STRIDE 1152          /* padded, /4 = 288 float4 */
#define X_STRIDE 1156            /* 1156*4 = 4624 B ≡ 16 mod 128 → conflict-free row strides */
#define RB 16
#define NTHREADS 256

// Transposed W1 scratch: W1T[j][k], zero-padded k in [1144,1152)
__device__ float g_W1T[HID * W1T_STRIDE];

__global__ void prep_kernel(const float* __restrict__ W1) {
    int idx = blockIdx.x * blockDim.x + threadIdx.x;
    if (idx < HID * W1T_STRIDE) {
        int j = idx / W1T_STRIDE;
        int k = idx - j * W1T_STRIDE;
        g_W1T[idx] = (k < IN_DIM) ? W1[k * HID + j] : 0.0f;
    }
}

__global__ __launch_bounds__(NTHREADS) void pnn_kernel(
    const int*   __restrict__ dense_ids,
    const int*   __restrict__ seq_ids,
    const float* __restrict__ tables_dense,
    const float* __restrict__ table_seq,
    const float* __restrict__ inner_w,
    const float* __restrict__ b1,
    const float* __restrict__ W2,
    const float* __restrict__ b2,
    float*       __restrict__ out)
{
    extern __shared__ float smem[];
    float* Xs   = smem;                    // RB * X_STRIDE
    float* hmat = smem + RB * X_STRIDE;    // RB * 32

    const int tid = threadIdx.x;
    const int l   = tid & 31;
    const int w   = tid >> 5;
    const int row0 = blockIdx.x * RB;

    // ---------------- Phase 1: gather (warp handles rows w and w+8) ----------------
    for (int rr = w; rr < RB; rr += 8) {
        const int row = row0 + rr;
        float* Xr = Xs + rr * X_STRIDE;
        const int* dids = dense_ids + row * ND;
        #pragma unroll
        for (int f = 0; f < ND; f++) {
            int id = __ldg(&dids[f]);
            const float2* src = (const float2*)(tables_dense + ((size_t)f * VV + (size_t)id) * DD);
            float2 v = __ldg(&src[l]);
            ((float2*)(Xr + f * DD))[l] = v;
        }
        // sequence mean (feature 15)
        const int* sids = seq_ids + row * SL;
        const float2* ts = (const float2*)table_seq;
        float ax = 0.f, ay = 0.f;
        #pragma unroll 5
        for (int s = 0; s < SL; s++) {
            int id = __ldg(&sids[s]);
            float2 v = __ldg(&ts[id * 32 + l]);
            ax += v.x; ay += v.y;
        }
        const float inv = 1.0f / 50.0f;
        ((float2*)(Xr + 15 * DD))[l] = make_float2(ax * inv, ay * inv);
        // zero-pad tail [1144, 1156)
        if (l < X_STRIDE - IN_DIM) Xr[IN_DIM + l] = 0.f;
    }
    __syncthreads();

    // ---------------- Phase 2: pairwise inner products ----------------
    {
        const int r    = l & 15;
        const int slot = l >> 4;
        const int q    = w * 2 + slot;           // 0..15
        const float* Xr = Xs + r * X_STRIDE;
        #pragma unroll
        for (int t = 0; t < 8; t++) {
            int p = q + 16 * t;
            if (p >= PAIRS) break;
            // decode pair (a, b), a < b, combinations order
            int a = 0, rem = p, cnt = 15;
            while (rem >= cnt) { rem -= cnt; cnt--; a++; }
            int bb = a + 1 + rem;
            const float4* xa = (const float4*)(Xr + a  * DD);
            const float4* xb = (const float4*)(Xr + bb * DD);
            const float4* ww = (const float4*)(inner_w + p * DD);
            float s0 = 0.f, s1 = 0.f;
            #pragma unroll
            for (int i = 0; i < DD / 4; i++) {
                float4 u = xa[i];
                float4 v = xb[i];
                float4 z = __ldg(&ww[i]);
                s0 += u.x * v.x * z.x + u.y * v.y * z.y;
                s1 += u.z * v.z * z.z + u.w * v.w * z.w;
            }
            Xs[r * X_STRIDE + FF * DD + p] = s0 + s1;
        }
    }
    __syncthreads();

    // ---------------- Phase 3: MLP layer 1 (each lane: 1 row x 2 hidden units) ----------------
    {
        const int r  = l & 15;
        const int jp = (l >> 4) + 2 * w;         // 0..15, active < 15
        if (jp < 15) {
            const int j0 = jp * 2;
            const float4* xr = (const float4*)(Xs + r * X_STRIDE);
            const float4* w0 = (const float4*)(g_W1T + j0 * W1T_STRIDE);
            const float4* w1 = (const float4*)(g_W1T + (j0 + 1) * W1T_STRIDE);
            float a0 = 0.f, a1 = 0.f, a2 = 0.f, a3 = 0.f;
            #pragma unroll 4
            for (int i = 0; i < W1T_STRIDE / 4; i++) {   // 288 iterations
                float4 x = xr[i];
                float4 u = __ldg(&w0[i]);
                float4 v = __ldg(&w1[i]);
                a0 += x.x * u.x + x.y * u.y;
                a1 += x.z * u.z + x.w * u.w;
                a2 += x.x * v.x + x.y * v.y;
                a3 += x.z * v.z + x.w * v.w;
            }
            float h0 = fmaxf(a0 + a1 + __ldg(&b1[j0    ]), 0.f);
            float h1 = fmaxf(a2 + a3 + __ldg(&b1[j0 + 1]), 0.f);
            hmat[r * 32 + j0    ] = h0 * __ldg(&W2[j0    ]);
            hmat[r * 32 + j0 + 1] = h1 * __ldg(&W2[j0 + 1]);
        }
    }
    __syncthreads();

    // ---------------- Phase 4: head reduction + sigmoid ----------------
    for (int rr = w; rr < RB; rr += 8) {
        float v = (l < HID) ? hmat[rr * 32 + l] : 0.f;
        #pragma unroll
        for (int o = 16; o > 0; o >>= 1) v += __shfl_xor_sync(0xffffffffu, v, o);
        if (l == 0) {
            float z = v + __ldg(&b2[0]);
            out[row0 + rr] = 1.0f / (1.0f + expf(-z));
        }
    }
}

extern "C" void kernel_launch(void* const* d_in, const int* in_sizes, int n_in,
                              void* d_out, int out_size) {
    const int*   dense_ids    = (const int*)  d_in[0];
    const int*   seq_ids      = (const int*)  d_in[1];
    const float* tables_dense = (const float*)d_in[2];
    const float* table_seq    = (const float*)d_in[3];
    const float* inner_w      = (const float*)d_in[4];
    const float* W1           = (const float*)d_in[5];
    const float* b1           = (const float*)d_in[6];
    const float* W2           = (const float*)d_in[7];
    const float* b2           = (const float*)d_in[8];
    float* out = (float*)d_out;

    (void)in_sizes; (void)n_in; (void)out_size;

    prep_kernel<<<(HID * W1T_STRIDE + 255) / 256, 256>>>(W1);

    const size_t smem = (size_t)(RB * X_STRIDE + RB * 32) * sizeof(float);  // 76032 B
    cudaFuncSetAttribute(pnn_kernel, cudaFuncAttributeMaxDynamicSharedMemorySize, (int)smem);
    pnn_kernel<<<BB / RB, NTHREADS, smem>>>(
        dense_ids, seq_ids, tables_dense, table_seq, inner_w, b1, W2, b2, out);
}